// round 10
// baseline (speedup 1.0000x reference)
#include <cuda_runtime.h>
#include <cuda_bf16.h>
#include <cstdint>

#define BSZ 128
#define DIM 1024
#define NCLS 32768
#define INV_TAU 20.0f
#define THRESH 20.0f
#define BN 64               // classes per block
#define NBLK (NCLS / BN)    // 512 gemm blocks
#define BK 32               // k per tile (32 fp8 bytes per row)
#define NT (DIM / BK)       // 32 iterations

// Scratch (device globals: no allocations allowed)
__device__ alignas(16) uint8_t g_a8[BSZ * DIM];         // e4m3 inputs
__device__ alignas(16) float g_pse[BSZ * NBLK];         // partial sumexp(s-20)
__device__ alignas(16) float g_pcn[BSZ * NBLK];         // partial count > 20
__device__ alignas(16) float g_pss[BSZ * NBLK];         // partial sum of s > 20
__device__ alignas(16) float g_st[BSZ];                 // s[target[b]]

// dynamic smem: A ring (cp.async) 3 x 6144 B (128 rows x 48B stride, 32B data),
// then B fp8 double buffer 2 x 3072 B (64 rows x 48B)
#define A_OFF 0
#define B_OFF 18432
#define SMEM_DYN 24576
#define RSTRIDE 48

__device__ __forceinline__ unsigned su32(const void* p) {
    return (unsigned)__cvta_generic_to_shared(p);
}
__device__ __forceinline__ uint32_t pack_e4m3x4(float4 v) {
    uint16_t lo, hi;
    asm("cvt.rn.satfinite.e4m3x2.f32 %0, %1, %2;" : "=h"(lo) : "f"(v.y), "f"(v.x));
    asm("cvt.rn.satfinite.e4m3x2.f32 %0, %1, %2;" : "=h"(hi) : "f"(v.w), "f"(v.z));
    return (uint32_t)lo | ((uint32_t)hi << 16);
}
__device__ __forceinline__ void cpasync16(uint32_t dst, const void* src) {
    asm volatile("cp.async.cg.shared.global [%0], [%1], 16;"
                 :: "r"(dst), "l"(src) : "memory");
}
__device__ __forceinline__ void mma_fp8(float* c, const uint32_t* a, const uint32_t* b) {
    asm volatile(
        "mma.sync.aligned.m16n8k32.row.col.f32.e4m3.e4m3.f32 "
        "{%0,%1,%2,%3}, {%4,%5,%6,%7}, {%8,%9}, {%0,%1,%2,%3};\n"
        : "+f"(c[0]), "+f"(c[1]), "+f"(c[2]), "+f"(c[3])
        : "r"(a[0]), "r"(a[1]), "r"(a[2]), "r"(a[3]), "r"(b[0]), "r"(b[1]));
}

// ---------------------------------------------------------------------------
// K0: convert inputs to e4m3 once
// ---------------------------------------------------------------------------
__global__ __launch_bounds__(256) void convert_inputs_kernel(const float* __restrict__ in) {
    int i = (blockIdx.x * 256 + threadIdx.x) * 4;
    float4 v = *reinterpret_cast<const float4*>(&in[i]);
    *reinterpret_cast<uint32_t*>(&g_a8[i]) = pack_e4m3x4(v);
}

// ---------------------------------------------------------------------------
// K1: GEMM (scores = inputs @ em^T * 20, fp8 QMMA) fused with em -> out_em
// copy and softmax statistics. BM=128 x BN=64 tiles -> 32-reg accumulators ->
// 3 CTAs/SM for cross-CTA overlap of memory and tensor phases.
// ---------------------------------------------------------------------------
__global__ __launch_bounds__(256, 3) void gemm_fused_kernel(const float* __restrict__ em,
                                                            float* __restrict__ out_em,
                                                            const int* __restrict__ targets) {
    extern __shared__ char dsm[];
    __shared__ float sRed[3][BSZ][4];
    __shared__ int sT[BSZ];

    const int tid = threadIdx.x;
    const int warp = tid >> 5;
    const int lane = tid & 31;
    const int warpM = warp >> 2;  // 0..1
    const int warpN = warp & 3;   // 0..3
    const int cBase = blockIdx.x * BN;

    if (tid < BSZ) sT[tid] = targets[tid];

    float acc[4][2][4];
#pragma unroll
    for (int i = 0; i < 4; i++)
#pragma unroll
        for (int j = 0; j < 2; j++)
#pragma unroll
            for (int k = 0; k < 4; k++) acc[i][j][k] = 0.0f;

    // ---- A via cp.async: tile kt -> stage kt%3 (256 x 16B chunks) ----
    auto issueA = [&](int kt2) {
        const int s2 = kt2 % 3;
        char* adst = dsm + A_OFF + s2 * 6144;
        int row = tid >> 1, q = tid & 1;
        cpasync16(su32(adst + row * RSTRIDE + q * 16),
                  (const char*)g_a8 + row * DIM + kt2 * BK + q * 16);
        asm volatile("cp.async.commit_group;" ::: "memory");
    };

    // ---- B: LDG into regs / stage regs -> out_em + fp8 smem ----
    float4 rbv[2];
    auto loadB = [&](int kt2) {
#pragma unroll
        for (int it = 0; it < 2; it++) {
            int c = tid + it * 256;
            int row = c >> 3, col4 = (c & 7) * 4;
            rbv[it] = __ldcs(reinterpret_cast<const float4*>(
                &em[(size_t)(cBase + row) * DIM + kt2 * BK + col4]));
        }
    };
    auto stageB = [&](int kt2, char* bdst) {
#pragma unroll
        for (int it = 0; it < 2; it++) {
            int c = tid + it * 256;
            int row = c >> 3, col4 = (c & 7) * 4;
            size_t gb = (size_t)(cBase + row) * DIM + kt2 * BK + col4;
            float4 v = rbv[it];
            __stcs(&out_em[gb], v.x);                                  // addr 4 mod 16
            __stcs(reinterpret_cast<float2*>(&out_em[gb + 1]),
                   make_float2(v.y, v.z));                             // addr 8 mod 16
            __stcs(&out_em[gb + 3], v.w);
            *reinterpret_cast<uint32_t*>(bdst + row * RSTRIDE + col4) = pack_e4m3x4(v);
        }
    };

    // ---- prologue ----
    issueA(0);
    issueA(1);
    loadB(0);
    stageB(0, dsm + B_OFF);
    asm volatile("cp.async.wait_group 1;" ::: "memory");
    __syncthreads();

    for (int kt = 0; kt < NT; kt++) {
        const char* as = dsm + A_OFF + (kt % 3) * 6144;
        const int bcur = kt & 1;
        const char* bb = dsm + B_OFF + bcur * 3072;
        const bool more = (kt + 1 < NT);

        if (more) loadB(kt + 1);
        if (kt + 2 < NT) issueA(kt + 2);
        else asm volatile("cp.async.commit_group;" ::: "memory");  // keep group count

        // ---- MMA: one k32 step ----
        uint32_t afr[4][4];
        {
            int r = lane & 15;
            int c16 = (lane >> 4) * 16;
#pragma unroll
            for (int i = 0; i < 4; i++) {
                unsigned addr = su32(as + (warpM * 64 + i * 16 + r) * RSTRIDE + c16);
                asm volatile(
                    "ldmatrix.sync.aligned.m8n8.x4.shared.b16 {%0,%1,%2,%3}, [%4];"
                    : "=r"(afr[i][0]), "=r"(afr[i][1]), "=r"(afr[i][2]), "=r"(afr[i][3])
                    : "r"(addr));
            }
        }
        uint32_t bfr[2][2];
        {
            int rb8 = lane & 7;
            int cb16 = ((lane >> 3) & 1) * 16;
#pragma unroll
            for (int j = 0; j < 2; j++) {
                unsigned addr = su32(bb + (warpN * 16 + j * 8 + rb8) * RSTRIDE + cb16);
                asm volatile(
                    "ldmatrix.sync.aligned.m8n8.x2.shared.b16 {%0,%1}, [%2];"
                    : "=r"(bfr[j][0]), "=r"(bfr[j][1])
                    : "r"(addr));
            }
        }
#pragma unroll
        for (int i = 0; i < 4; i++)
#pragma unroll
            for (int j = 0; j < 2; j++) mma_fp8(acc[i][j], afr[i], bfr[j]);

        if (more) stageB(kt + 1, dsm + B_OFF + (bcur ^ 1) * 3072);
        asm volatile("cp.async.wait_group 1;" ::: "memory");
        __syncthreads();
    }

    // ---- fused epilogue: per-row partial statistics ----
    const int r = lane >> 2;
#pragma unroll
    for (int i = 0; i < 4; i++) {
#pragma unroll
        for (int half = 0; half < 2; half++) {
            int bb2 = warpM * 64 + i * 16 + r + half * 8;   // global sample index
            int tgt = sT[bb2];
            float se = 0.0f, cn = 0.0f, ss = 0.0f;
#pragma unroll
            for (int j = 0; j < 2; j++) {
                int cc = cBase + warpN * 16 + j * 8 + (lane & 3) * 2;
                float v0 = acc[i][j][half * 2 + 0] * INV_TAU;
                float v1 = acc[i][j][half * 2 + 1] * INV_TAU;
                se += __expf(v0 - 20.0f) + __expf(v1 - 20.0f);
                if (v0 > THRESH) { cn += 1.0f; ss += v0; }
                if (v1 > THRESH) { cn += 1.0f; ss += v1; }
                if (cc == tgt) g_st[bb2] = v0;
                if (cc + 1 == tgt) g_st[bb2] = v1;
            }
#pragma unroll
            for (int o = 1; o < 4; o <<= 1) {
                se += __shfl_xor_sync(~0u, se, o);
                cn += __shfl_xor_sync(~0u, cn, o);
                ss += __shfl_xor_sync(~0u, ss, o);
            }
            if ((lane & 3) == 0) {
                sRed[0][bb2][warpN] = se;
                sRed[1][bb2][warpN] = cn;
                sRed[2][bb2][warpN] = ss;
            }
        }
    }
    __syncthreads();
    if (tid < BSZ) {
        g_pse[tid * NBLK + blockIdx.x] =
            sRed[0][tid][0] + sRed[0][tid][1] + sRed[0][tid][2] + sRed[0][tid][3];
        g_pcn[tid * NBLK + blockIdx.x] =
            sRed[1][tid][0] + sRed[1][tid][1] + sRed[1][tid][2] + sRed[1][tid][3];
        g_pss[tid * NBLK + blockIdx.x] =
            sRed[2][tid][0] + sRed[2][tid][1] + sRed[2][tid][2] + sRed[2][tid][3];
    }
}

// ---------------------------------------------------------------------------
// K2: fused scatter + loss.
// Blocks 0..127: EMA scatter chains (O(1) head detection via smem + ballot).
// Block 128: reduce partials, write ks and final loss mean.
// ---------------------------------------------------------------------------
__global__ __launch_bounds__(256) void scatter_loss_kernel(const float* __restrict__ inputs,
                                                           const int* __restrict__ targets,
                                                           const int* __restrict__ epoch,
                                                           float* __restrict__ out_em,
                                                           float* __restrict__ out) {
    const int t = threadIdx.x;
    const int warp = t >> 5;
    const int lane = t & 31;

    if (blockIdx.x == BSZ) {
        __shared__ float sLoss[BSZ];
        for (int b = warp; b < BSZ; b += 8) {
            float se = 0.0f, cn = 0.0f, ss = 0.0f;
#pragma unroll
            for (int i = lane; i < NBLK; i += 32) {
                se += g_pse[b * NBLK + i];
                cn += g_pcn[b * NBLK + i];
                ss += g_pss[b * NBLK + i];
            }
#pragma unroll
            for (int o = 16; o; o >>= 1) {
                se += __shfl_xor_sync(~0u, se, o);
                cn += __shfl_xor_sync(~0u, cn, o);
                ss += __shfl_xor_sync(~0u, ss, o);
            }
            if (lane == 0) {
                float st = g_st[b];
                float lse = 20.0f + logf(se);
                float logpt = st - lse;
                int n = (int)(cn + 0.5f);
                float loss;
                if (n > 1) {
                    float kk = 1.0f / ((float)n * logf((float)n));
                    int ta = (st > THRESH) ? 1 : 0;
                    float extra = kk * ((ss - (ta ? st : 0.0f)) - (float)(n - ta) * lse);
                    loss = -(extra + logpt);
                } else {
                    loss = -logpt;
                }
                sLoss[b] = loss;
                out[1 + b] = cn;  // ks
            }
        }
        __syncthreads();
        if (t == 0) {
            float acc = 0.0f;
            for (int i = 0; i < BSZ; i++) acc += sLoss[i];
            out[0] = acc / (float)BSZ;
        }
        return;
    }

    // ---- scatter block ----
    __shared__ int sT[BSZ];
    __shared__ float red[8];
    __shared__ float bc;
    if (t < BSZ) sT[t] = targets[t];
    __syncthreads();

    const int b = blockIdx.x;
    const int y = sT[b];
    int match = (t < b && sT[t] == y) ? 1 : 0;
    if (__syncthreads_or(match)) return;  // not the chain head (uniform)

    const float mu = fminf(0.4f / 60.0f * (float)(epoch[0] + 1), 1.0f);
    const float omu = 1.0f - mu;

    const size_t rbase = (size_t)y * DIM + t * 4;
    float row[4];
#pragma unroll
    for (int q = 0; q < 4; q++) row[q] = out_em[rbase + q];  // scalar: base 4 mod 16

    for (int j = b; j < BSZ; j++) {
        if (sT[j] != y) continue;  // uniform across block (smem)
        float4 x = *reinterpret_cast<const float4*>(&inputs[(size_t)j * DIM + t * 4]);
        float v0 = mu * row[0] + omu * x.x;
        float v1 = mu * row[1] + omu * x.y;
        float v2 = mu * row[2] + omu * x.z;
        float v3 = mu * row[3] + omu * x.w;
        float sq = v0 * v0 + v1 * v1 + v2 * v2 + v3 * v3;
#pragma unroll
        for (int o = 16; o; o >>= 1) sq += __shfl_xor_sync(~0u, sq, o);
        if (lane == 0) red[warp] = sq;
        __syncthreads();
        if (t == 0) {
            float s = 0.0f;
#pragma unroll
            for (int i = 0; i < 8; i++) s += red[i];
            bc = s;
        }
        __syncthreads();
        float rn = rsqrtf(bc);
        row[0] = v0 * rn; row[1] = v1 * rn; row[2] = v2 * rn; row[3] = v3 * rn;
    }
#pragma unroll
    for (int q = 0; q < 4; q++) out_em[rbase + q] = row[q];
}

// ---------------------------------------------------------------------------
// Entry point. Output layout (float32): [loss(1), ks(128), new_em(32768*1024)]
// ---------------------------------------------------------------------------
extern "C" void kernel_launch(void* const* d_in, const int* in_sizes, int n_in,
                              void* d_out, int out_size) {
    const float* inputs = (const float*)d_in[0];
    const float* em = (const float*)d_in[1];
    const int* targets = (const int*)d_in[2];
    const int* epoch = (const int*)d_in[3];
    float* out = (float*)d_out;
    float* out_em = out + 1 + BSZ;

    static bool attr_set = false;
    if (!attr_set) {
        cudaFuncSetAttribute(gemm_fused_kernel,
                             cudaFuncAttributeMaxDynamicSharedMemorySize, SMEM_DYN);
        attr_set = true;
    }

    convert_inputs_kernel<<<128, 256>>>(inputs);
    gemm_fused_kernel<<<NBLK, 256, SMEM_DYN>>>(em, out_em, targets);
    scatter_loss_kernel<<<BSZ + 1, 256>>>(inputs, targets, epoch, out_em, out);
}

// round 12
// speedup vs baseline: 1.2191x; 1.2191x over previous
#include <cuda_runtime.h>
#include <cuda_bf16.h>
#include <cstdint>

#define BSZ 128
#define DIM 1024
#define NCLS 32768
#define INV_TAU 20.0f
#define THRESH 20.0f
#define BN 128
#define NBLK (NCLS / BN)    // 256 gemm blocks
#define BK 32               // k per tile (32 fp8 bytes per row)
#define NT (DIM / BK)       // 32 iterations

// Scratch (device globals: no allocations allowed)
__device__ alignas(16) uint8_t g_a8[BSZ * DIM];         // e4m3 inputs
__device__ alignas(16) float g_pse[BSZ * NBLK];         // partial sumexp(s-20)
__device__ alignas(16) float g_pcn[BSZ * NBLK];         // partial count > 20
__device__ alignas(16) float g_pss[BSZ * NBLK];         // partial sum of s > 20
__device__ alignas(16) float g_st[BSZ];                 // s[target[b]]

// dynamic smem:
//   A ring   3 x 6144  (fp8, 128 rows x 48B stride)          @ 0
//   Bf32 ring 3 x 16384 (fp32, 128 rows x 128B)              @ 18432
//   Bf8 bufs 2 x 6144  (fp8, 128 rows x 48B stride)          @ 67584
#define A_OFF 0
#define BF32_OFF 18432
#define BF8_OFF 67584
#define SMEM_DYN 79872
#define RSTRIDE 48

__device__ __forceinline__ unsigned su32(const void* p) {
    return (unsigned)__cvta_generic_to_shared(p);
}
__device__ __forceinline__ uint32_t pack_e4m3x4(float4 v) {
    uint16_t lo, hi;
    asm("cvt.rn.satfinite.e4m3x2.f32 %0, %1, %2;" : "=h"(lo) : "f"(v.y), "f"(v.x));
    asm("cvt.rn.satfinite.e4m3x2.f32 %0, %1, %2;" : "=h"(hi) : "f"(v.w), "f"(v.z));
    return (uint32_t)lo | ((uint32_t)hi << 16);
}
__device__ __forceinline__ void cpasync16(uint32_t dst, const void* src) {
    asm volatile("cp.async.cg.shared.global [%0], [%1], 16;"
                 :: "r"(dst), "l"(src) : "memory");
}
__device__ __forceinline__ void mma_fp8(float* c, const uint32_t* a, const uint32_t* b) {
    asm volatile(
        "mma.sync.aligned.m16n8k32.row.col.f32.e4m3.e4m3.f32 "
        "{%0,%1,%2,%3}, {%4,%5,%6,%7}, {%8,%9}, {%0,%1,%2,%3};\n"
        : "+f"(c[0]), "+f"(c[1]), "+f"(c[2]), "+f"(c[3])
        : "r"(a[0]), "r"(a[1]), "r"(a[2]), "r"(a[3]), "r"(b[0]), "r"(b[1]));
}

// ---------------------------------------------------------------------------
// K0: convert inputs to e4m3 once
// ---------------------------------------------------------------------------
__global__ __launch_bounds__(256) void convert_inputs_kernel(const float* __restrict__ in) {
    int i = (blockIdx.x * 256 + threadIdx.x) * 4;
    float4 v = *reinterpret_cast<const float4*>(&in[i]);
    *reinterpret_cast<uint32_t*>(&g_a8[i]) = pack_e4m3x4(v);
}

// ---------------------------------------------------------------------------
// K1: fp8 GEMM (scores = inputs @ em^T * 20) fused with em -> out_em copy and
// softmax statistics. Deep cp.async pipeline:
//   A: fp8 ring (3 stages).  B: fp32 ring (3 stages) -> deferred staging
//   (LDS -> STG copy -> cvt fp8 -> STS) one iteration ahead of the mma that
//   consumes it. One barrier + one wait_group per iteration; no LDG on the
//   critical path.
// Group G_k (committed in iter k) = {A(k+2), Bf32(k+3)}.
// ---------------------------------------------------------------------------
__global__ __launch_bounds__(256, 2) void gemm_fused_kernel(const float* __restrict__ em,
                                                            float* __restrict__ out_em,
                                                            const int* __restrict__ targets) {
    extern __shared__ char dsm[];
    __shared__ float sRed[3][BSZ][4];
    __shared__ int sT[BSZ];

    const int tid = threadIdx.x;
    const int warp = tid >> 5;
    const int lane = tid & 31;
    const int warpM = warp >> 2;  // 0..1
    const int warpN = warp & 3;   // 0..3
    const int cBase = blockIdx.x * BN;

    if (tid < BSZ) sT[tid] = targets[tid];

    float acc[4][4][4];
#pragma unroll
    for (int i = 0; i < 4; i++)
#pragma unroll
        for (int j = 0; j < 4; j++)
#pragma unroll
            for (int k = 0; k < 4; k++) acc[i][j][k] = 0.0f;

    // per-thread coords
    const int aRow = tid >> 1, aQ = tid & 1;            // A: 256 x 16B chunks

    auto issueA = [&](int kt2) {                         // A(kt2) -> ring kt2%3
        char* adst = dsm + A_OFF + (kt2 % 3) * 6144;
        cpasync16(su32(adst + aRow * RSTRIDE + aQ * 16),
                  (const char*)g_a8 + aRow * DIM + kt2 * BK + aQ * 16);
    };
    auto issueB32 = [&](int kt2) {                       // Bf32(kt2) -> ring kt2%3
        char* bdst = dsm + BF32_OFF + (kt2 % 3) * 16384;
#pragma unroll
        for (int it = 0; it < 4; it++) {                 // FULL tile: 1024 chunks
            int c = tid + it * 256;                      // 0..1023
            int row = c >> 3, q = c & 7;
            cpasync16(su32(bdst + row * 128 + q * 16),
                      (const char*)em +
                          ((size_t)(cBase + row) * DIM + kt2 * BK + q * 4) * 4);
        }
    };
    // stage tile kt2 from Bf32 ring: out_em copy + fp8 pack into Bf8[kt2&1]
    auto stageB = [&](int kt2) {
        const char* bsrc = dsm + BF32_OFF + (kt2 % 3) * 16384;
        char* bdst = dsm + BF8_OFF + (kt2 & 1) * 6144;
#pragma unroll
        for (int it = 0; it < 4; it++) {
            int c = tid + it * 256;                      // 0..1023
            int row = c >> 3, col4 = (c & 7) * 4;
            float4 v = *reinterpret_cast<const float4*>(bsrc + row * 128 + col4 * 4);
            size_t gb = (size_t)(cBase + row) * DIM + kt2 * BK + col4;
            __stcs(&out_em[gb], v.x);                                  // addr 4 mod 16
            __stcs(reinterpret_cast<float2*>(&out_em[gb + 1]),
                   make_float2(v.y, v.z));                             // addr 8 mod 16
            __stcs(&out_em[gb + 3], v.w);
            *reinterpret_cast<uint32_t*>(bdst + row * RSTRIDE + col4) = pack_e4m3x4(v);
        }
    };

    // ---- prologue ----
    issueA(0); issueB32(1);
    asm volatile("cp.async.commit_group;" ::: "memory");   // G_{-2}
    issueA(1); issueB32(2);
    asm volatile("cp.async.commit_group;" ::: "memory");   // G_{-1}
    // tile 0 B: direct LDG -> copy + fp8 buf 0
    {
        char* bdst = dsm + BF8_OFF;
#pragma unroll
        for (int it = 0; it < 4; it++) {
            int c = tid + it * 256;
            int row = c >> 3, col4 = (c & 7) * 4;
            size_t gb = (size_t)(cBase + row) * DIM + col4;
            float4 v = __ldcs(reinterpret_cast<const float4*>(&em[gb]));
            __stcs(&out_em[gb], v.x);
            __stcs(reinterpret_cast<float2*>(&out_em[gb + 1]), make_float2(v.y, v.z));
            __stcs(&out_em[gb + 3], v.w);
            *reinterpret_cast<uint32_t*>(bdst + row * RSTRIDE + col4) = pack_e4m3x4(v);
        }
    }
    asm volatile("cp.async.wait_group 1;" ::: "memory");    // G_{-2}: A(0), Bf32(1)
    __syncthreads();

    for (int kt = 0; kt < NT; kt++) {
        const char* as = dsm + A_OFF + (kt % 3) * 6144;
        const char* bb = dsm + BF8_OFF + (kt & 1) * 6144;

        // ---- fragments for tile kt ----
        uint32_t afr[4][4];
        {
            int r = lane & 15;
            int c16 = (lane >> 4) * 16;
#pragma unroll
            for (int i = 0; i < 4; i++) {
                unsigned addr = su32(as + (warpM * 64 + i * 16 + r) * RSTRIDE + c16);
                asm volatile(
                    "ldmatrix.sync.aligned.m8n8.x4.shared.b16 {%0,%1,%2,%3}, [%4];"
                    : "=r"(afr[i][0]), "=r"(afr[i][1]), "=r"(afr[i][2]), "=r"(afr[i][3])
                    : "r"(addr));
            }
        }
        uint32_t bfr[4][2];
        {
            int rb8 = lane & 7;
            int cb16 = ((lane >> 3) & 1) * 16;
#pragma unroll
            for (int j = 0; j < 4; j++) {
                unsigned addr = su32(bb + (warpN * 32 + j * 8 + rb8) * RSTRIDE + cb16);
                asm volatile(
                    "ldmatrix.sync.aligned.m8n8.x2.shared.b16 {%0,%1}, [%2];"
                    : "=r"(bfr[j][0]), "=r"(bfr[j][1])
                    : "r"(addr));
            }
        }

        // ---- stage tile kt+1 (overlaps mma issue below) ----
        if (kt + 1 < NT) stageB(kt + 1);

        // ---- issue group G_kt = {A(kt+2), Bf32(kt+3)} ----
        if (kt + 2 < NT) issueA(kt + 2);
        if (kt + 3 < NT) issueB32(kt + 3);
        asm volatile("cp.async.commit_group;" ::: "memory");

        // ---- mma ----
#pragma unroll
        for (int i = 0; i < 4; i++)
#pragma unroll
            for (int j = 0; j < 4; j++) mma_fp8(acc[i][j], afr[i], bfr[j]);

        asm volatile("cp.async.wait_group 1;" ::: "memory");  // G_{kt-1} done
        __syncthreads();
    }

    // ---- fused epilogue: per-row partial statistics ----
    const int r = lane >> 2;
#pragma unroll
    for (int i = 0; i < 4; i++) {
#pragma unroll
        for (int half = 0; half < 2; half++) {
            int bb2 = warpM * 64 + i * 16 + r + half * 8;   // global sample index
            int tgt = sT[bb2];
            float se = 0.0f, cn = 0.0f, ss = 0.0f;
#pragma unroll
            for (int j = 0; j < 4; j++) {
                int cc = cBase + warpN * 32 + j * 8 + (lane & 3) * 2;
                float v0 = acc[i][j][half * 2 + 0] * INV_TAU;
                float v1 = acc[i][j][half * 2 + 1] * INV_TAU;
                se += __expf(v0 - 20.0f) + __expf(v1 - 20.0f);
                if (v0 > THRESH) { cn += 1.0f; ss += v0; }
                if (v1 > THRESH) { cn += 1.0f; ss += v1; }
                if (cc == tgt) g_st[bb2] = v0;
                if (cc + 1 == tgt) g_st[bb2] = v1;
            }
#pragma unroll
            for (int o = 1; o < 4; o <<= 1) {
                se += __shfl_xor_sync(~0u, se, o);
                cn += __shfl_xor_sync(~0u, cn, o);
                ss += __shfl_xor_sync(~0u, ss, o);
            }
            if ((lane & 3) == 0) {
                sRed[0][bb2][warpN] = se;
                sRed[1][bb2][warpN] = cn;
                sRed[2][bb2][warpN] = ss;
            }
        }
    }
    __syncthreads();
    if (tid < BSZ) {
        g_pse[tid * NBLK + blockIdx.x] =
            sRed[0][tid][0] + sRed[0][tid][1] + sRed[0][tid][2] + sRed[0][tid][3];
        g_pcn[tid * NBLK + blockIdx.x] =
            sRed[1][tid][0] + sRed[1][tid][1] + sRed[1][tid][2] + sRed[1][tid][3];
        g_pss[tid * NBLK + blockIdx.x] =
            sRed[2][tid][0] + sRed[2][tid][1] + sRed[2][tid][2] + sRed[2][tid][3];
    }
}

// ---------------------------------------------------------------------------
// K2: fused scatter + loss.
// Blocks 0..127: EMA scatter chains (O(1) head detection via smem + ballot).
// Block 128: reduce partials, write ks and final loss mean.
// ---------------------------------------------------------------------------
__global__ __launch_bounds__(256) void scatter_loss_kernel(const float* __restrict__ inputs,
                                                           const int* __restrict__ targets,
                                                           const int* __restrict__ epoch,
                                                           float* __restrict__ out_em,
                                                           float* __restrict__ out) {
    const int t = threadIdx.x;
    const int warp = t >> 5;
    const int lane = t & 31;

    if (blockIdx.x == BSZ) {
        __shared__ float sLoss[BSZ];
        for (int b = warp; b < BSZ; b += 8) {
            float se = 0.0f, cn = 0.0f, ss = 0.0f;
#pragma unroll
            for (int i = lane; i < NBLK; i += 32) {
                se += g_pse[b * NBLK + i];
                cn += g_pcn[b * NBLK + i];
                ss += g_pss[b * NBLK + i];
            }
#pragma unroll
            for (int o = 16; o; o >>= 1) {
                se += __shfl_xor_sync(~0u, se, o);
                cn += __shfl_xor_sync(~0u, cn, o);
                ss += __shfl_xor_sync(~0u, ss, o);
            }
            if (lane == 0) {
                float st = g_st[b];
                float lse = 20.0f + logf(se);
                float logpt = st - lse;
                int n = (int)(cn + 0.5f);
                float loss;
                if (n > 1) {
                    float kk = 1.0f / ((float)n * logf((float)n));
                    int ta = (st > THRESH) ? 1 : 0;
                    float extra = kk * ((ss - (ta ? st : 0.0f)) - (float)(n - ta) * lse);
                    loss = -(extra + logpt);
                } else {
                    loss = -logpt;
                }
                sLoss[b] = loss;
                out[1 + b] = cn;  // ks
            }
        }
        __syncthreads();
        if (t == 0) {
            float acc = 0.0f;
            for (int i = 0; i < BSZ; i++) acc += sLoss[i];
            out[0] = acc / (float)BSZ;
        }
        return;
    }

    // ---- scatter block ----
    __shared__ int sT[BSZ];
    __shared__ float red[8];
    __shared__ float bc;
    if (t < BSZ) sT[t] = targets[t];
    __syncthreads();

    const int b = blockIdx.x;
    const int y = sT[b];
    int match = (t < b && sT[t] == y) ? 1 : 0;
    if (__syncthreads_or(match)) return;  // not the chain head (uniform)

    const float mu = fminf(0.4f / 60.0f * (float)(epoch[0] + 1), 1.0f);
    const float omu = 1.0f - mu;

    const size_t rbase = (size_t)y * DIM + t * 4;
    float row[4];
#pragma unroll
    for (int q = 0; q < 4; q++) row[q] = out_em[rbase + q];  // scalar: base 4 mod 16

    for (int j = b; j < BSZ; j++) {
        if (sT[j] != y) continue;  // uniform across block (smem)
        float4 x = *reinterpret_cast<const float4*>(&inputs[(size_t)j * DIM + t * 4]);
        float v0 = mu * row[0] + omu * x.x;
        float v1 = mu * row[1] + omu * x.y;
        float v2 = mu * row[2] + omu * x.z;
        float v3 = mu * row[3] + omu * x.w;
        float sq = v0 * v0 + v1 * v1 + v2 * v2 + v3 * v3;
#pragma unroll
        for (int o = 16; o; o >>= 1) sq += __shfl_xor_sync(~0u, sq, o);
        if (lane == 0) red[warp] = sq;
        __syncthreads();
        if (t == 0) {
            float s = 0.0f;
#pragma unroll
            for (int i = 0; i < 8; i++) s += red[i];
            bc = s;
        }
        __syncthreads();
        float rn = rsqrtf(bc);
        row[0] = v0 * rn; row[1] = v1 * rn; row[2] = v2 * rn; row[3] = v3 * rn;
    }
#pragma unroll
    for (int q = 0; q < 4; q++) out_em[rbase + q] = row[q];
}

// ---------------------------------------------------------------------------
// Entry point. Output layout (float32): [loss(1), ks(128), new_em(32768*1024)]
// ---------------------------------------------------------------------------
extern "C" void kernel_launch(void* const* d_in, const int* in_sizes, int n_in,
                              void* d_out, int out_size) {
    const float* inputs = (const float*)d_in[0];
    const float* em = (const float*)d_in[1];
    const int* targets = (const int*)d_in[2];
    const int* epoch = (const int*)d_in[3];
    float* out = (float*)d_out;
    float* out_em = out + 1 + BSZ;

    static bool attr_set = false;
    if (!attr_set) {
        cudaFuncSetAttribute(gemm_fused_kernel,
                             cudaFuncAttributeMaxDynamicSharedMemorySize, SMEM_DYN);
        attr_set = true;
    }

    convert_inputs_kernel<<<128, 256>>>(inputs);
    gemm_fused_kernel<<<NBLK, 256, SMEM_DYN>>>(em, out_em, targets);
    scatter_loss_kernel<<<BSZ + 1, 256>>>(inputs, targets, epoch, out_em, out);
}

// round 13
// speedup vs baseline: 1.4372x; 1.1789x over previous
#include <cuda_runtime.h>
#include <cuda_bf16.h>
#include <cstdint>

#define BSZ 128
#define DIM 1024
#define NCLS 32768
#define INV_TAU 20.0f
#define THRESH 20.0f
#define BN 256
#define NBLK (NCLS / BN)    // 128 gemm blocks (one wave)
#define BK 32               // k per tile (32 fp8 bytes per row)
#define NT (DIM / BK)       // 32 iterations

#define NCONS 512           // 16 consumer warps
#define NPROD 128           // 4 producer warps
#define NTHREADS 640

// Scratch (device globals: no allocations allowed)
__device__ alignas(16) uint8_t g_a8[BSZ * DIM];         // e4m3 inputs
__device__ alignas(16) float g_pse[BSZ * NBLK];         // partial sumexp(s-20)
__device__ alignas(16) float g_pcn[BSZ * NBLK];         // partial count > 20
__device__ alignas(16) float g_pss[BSZ * NBLK];         // partial sum of s > 20
__device__ alignas(16) float g_st[BSZ];                 // s[target[b]]

// dynamic smem rings (3 slots each):
//   A fp8   : 128 rows x 48B stride  = 6144/slot   @ 0
//   B fp8   : 256 rows x 48B stride  = 12288/slot  @ 18432
//   B fp32  : 256 rows x 128B        = 32768/slot  @ 55296
#define A_OFF 0
#define B8_OFF 18432
#define BF32_OFF 55296
#define SMEM_DYN 153600
#define RSTRIDE 48

// named barriers: 1+s = FULL(s), 4+s = EMPTY(s)
#define BAR_FULL(s) (1 + (s))
#define BAR_EMPTY(s) (4 + (s))

__device__ __forceinline__ void bar_sync(int id) {
    asm volatile("bar.sync %0, %1;" :: "r"(id), "n"(NTHREADS) : "memory");
}
__device__ __forceinline__ void bar_arrive(int id) {
    asm volatile("bar.arrive %0, %1;" :: "r"(id), "n"(NTHREADS) : "memory");
}
__device__ __forceinline__ unsigned su32(const void* p) {
    return (unsigned)__cvta_generic_to_shared(p);
}
__device__ __forceinline__ uint32_t pack_e4m3x4(float4 v) {
    uint16_t lo, hi;
    asm("cvt.rn.satfinite.e4m3x2.f32 %0, %1, %2;" : "=h"(lo) : "f"(v.y), "f"(v.x));
    asm("cvt.rn.satfinite.e4m3x2.f32 %0, %1, %2;" : "=h"(hi) : "f"(v.w), "f"(v.z));
    return (uint32_t)lo | ((uint32_t)hi << 16);
}
__device__ __forceinline__ void cpasync16(uint32_t dst, const void* src) {
    asm volatile("cp.async.cg.shared.global [%0], [%1], 16;"
                 :: "r"(dst), "l"(src) : "memory");
}
__device__ __forceinline__ void mma_fp8(float* c, const uint32_t* a, const uint32_t* b) {
    asm volatile(
        "mma.sync.aligned.m16n8k32.row.col.f32.e4m3.e4m3.f32 "
        "{%0,%1,%2,%3}, {%4,%5,%6,%7}, {%8,%9}, {%0,%1,%2,%3};\n"
        : "+f"(c[0]), "+f"(c[1]), "+f"(c[2]), "+f"(c[3])
        : "r"(a[0]), "r"(a[1]), "r"(a[2]), "r"(a[3]), "r"(b[0]), "r"(b[1]));
}

// ---------------------------------------------------------------------------
// K0: convert inputs to e4m3 once
// ---------------------------------------------------------------------------
__global__ __launch_bounds__(256) void convert_inputs_kernel(const float* __restrict__ in) {
    int i = (blockIdx.x * 256 + threadIdx.x) * 4;
    float4 v = *reinterpret_cast<const float4*>(&in[i]);
    *reinterpret_cast<uint32_t*>(&g_a8[i]) = pack_e4m3x4(v);
}

// ---------------------------------------------------------------------------
// K1: warp-specialized fp8 GEMM (scores = inputs @ em^T * 20) fused with
// em -> out_em copy and softmax statistics.
//   warps 0..15  : consumers — ldmatrix + QMMA only (32x64 tile each)
//   warps 16..19 : producers — cp.async rings, out_em copy, fp8 staging
// 3-slot rings; named-barrier full/empty handshake.
// ---------------------------------------------------------------------------
__global__ __launch_bounds__(NTHREADS, 1) void gemm_fused_kernel(
    const float* __restrict__ em,
    float* __restrict__ out_em,
    const int* __restrict__ targets) {
    extern __shared__ char dsm[];
    __shared__ float sRed[3][BSZ][4];
    __shared__ int sT[BSZ];

    const int tid = threadIdx.x;
    const int warp = tid >> 5;
    const int lane = tid & 31;
    const int cBase = blockIdx.x * BN;

    if (tid < BSZ) sT[tid] = targets[tid];
    __syncthreads();  // sT visible before epilogue; also orders nothing else

    if (warp >= 16) {
        // =================== PRODUCER ===================
        const int p = tid - NCONS;  // 0..127

        auto issueTile = [&](int t) {
            const int slot = t % 3;
            char* bdst = dsm + BF32_OFF + slot * 32768;
#pragma unroll
            for (int j = 0; j < 16; j++) {
                int c = p + j * 128;          // 0..2047
                int row = c >> 3, q = c & 7;
                cpasync16(su32(bdst + row * 128 + q * 16),
                          (const char*)em +
                              ((size_t)(cBase + row) * DIM + t * BK + q * 4) * 4);
            }
            char* adst = dsm + A_OFF + slot * 6144;
#pragma unroll
            for (int h2 = 0; h2 < 2; h2++) {
                int c = p + h2 * 128;         // 0..255
                int row = c >> 1, h = c & 1;
                cpasync16(su32(adst + row * RSTRIDE + h * 16),
                          (const char*)g_a8 + row * DIM + t * BK + h * 16);
            }
        };

        issueTile(0);
        asm volatile("cp.async.commit_group;" ::: "memory");
        issueTile(1);
        asm volatile("cp.async.commit_group;" ::: "memory");

        for (int kt = 0; kt < NT; kt++) {
            const int t = kt + 2;
            if (t < NT) {
                if (t >= 3) bar_sync(BAR_EMPTY(t % 3));  // slot freed by consumers
                issueTile(t);
            }
            asm volatile("cp.async.commit_group;" ::: "memory");
            asm volatile("cp.async.wait_group 2;" ::: "memory");  // tile kt landed

            // ---- stage tile kt: fp32 ring -> out_em copy + fp8 ring ----
            const int slot = kt % 3;
            const char* bsrc = dsm + BF32_OFF + slot * 32768;
            char* b8 = dsm + B8_OFF + slot * 12288;
#pragma unroll
            for (int j = 0; j < 16; j++) {
                int c = p + j * 128;
                int row = c >> 3, q = c & 7;
                float4 v = *reinterpret_cast<const float4*>(bsrc + row * 128 + q * 16);
                size_t gb = (size_t)(cBase + row) * DIM + kt * BK + q * 4;
                __stcs(&out_em[gb], v.x);                              // addr 4 mod 16
                __stcs(reinterpret_cast<float2*>(&out_em[gb + 1]),
                       make_float2(v.y, v.z));                         // addr 8 mod 16
                __stcs(&out_em[gb + 3], v.w);
                *reinterpret_cast<uint32_t*>(b8 + row * RSTRIDE + q * 4) = pack_e4m3x4(v);
            }
            bar_arrive(BAR_FULL(slot));
        }
    } else {
        // =================== CONSUMER ===================
        const int wR = warp & 3;   // M row-group (32 rows)
        const int wC = warp >> 2;  // N col-group (64 cols)

        float acc[2][8][4];
#pragma unroll
        for (int i = 0; i < 2; i++)
#pragma unroll
            for (int j = 0; j < 8; j++)
#pragma unroll
                for (int k = 0; k < 4; k++) acc[i][j][k] = 0.0f;

        const int ar = lane & 15;
        const int ah = (lane >> 4) * 16;
        const int br = lane & 7;
        const int bh = ((lane >> 3) & 1) * 16;

        for (int kt = 0; kt < NT; kt++) {
            const int slot = kt % 3;
            bar_sync(BAR_FULL(slot));
            const char* as = dsm + A_OFF + slot * 6144;
            const char* bs = dsm + B8_OFF + slot * 12288;

            uint32_t afr[2][4];
#pragma unroll
            for (int i = 0; i < 2; i++) {
                unsigned addr = su32(as + (wR * 32 + i * 16 + ar) * RSTRIDE + ah);
                asm volatile(
                    "ldmatrix.sync.aligned.m8n8.x4.shared.b16 {%0,%1,%2,%3}, [%4];"
                    : "=r"(afr[i][0]), "=r"(afr[i][1]), "=r"(afr[i][2]), "=r"(afr[i][3])
                    : "r"(addr));
            }
#pragma unroll
            for (int j = 0; j < 8; j++) {
                uint32_t bfr[2];
                unsigned addr = su32(bs + (wC * 64 + j * 8 + br) * RSTRIDE + bh);
                asm volatile(
                    "ldmatrix.sync.aligned.m8n8.x2.shared.b16 {%0,%1}, [%2];"
                    : "=r"(bfr[0]), "=r"(bfr[1])
                    : "r"(addr));
                mma_fp8(acc[0][j], afr[0], bfr);
                mma_fp8(acc[1][j], afr[1], bfr);
            }
            bar_arrive(BAR_EMPTY(slot));
        }

        // ---- fused epilogue: per-row partial statistics ----
#pragma unroll
        for (int i = 0; i < 2; i++) {
#pragma unroll
            for (int half = 0; half < 2; half++) {
                int bb = wR * 32 + i * 16 + (lane >> 2) + half * 8;  // sample index
                int tgt = sT[bb];
                float se = 0.0f, cn = 0.0f, ss = 0.0f;
#pragma unroll
                for (int j = 0; j < 8; j++) {
                    int cc = cBase + wC * 64 + j * 8 + (lane & 3) * 2;
                    float v0 = acc[i][j][half * 2 + 0] * INV_TAU;
                    float v1 = acc[i][j][half * 2 + 1] * INV_TAU;
                    se += __expf(v0 - 20.0f) + __expf(v1 - 20.0f);
                    if (v0 > THRESH) { cn += 1.0f; ss += v0; }
                    if (v1 > THRESH) { cn += 1.0f; ss += v1; }
                    if (cc == tgt) g_st[bb] = v0;
                    if (cc + 1 == tgt) g_st[bb] = v1;
                }
#pragma unroll
                for (int o = 1; o < 4; o <<= 1) {
                    se += __shfl_xor_sync(~0u, se, o);
                    cn += __shfl_xor_sync(~0u, cn, o);
                    ss += __shfl_xor_sync(~0u, ss, o);
                }
                if ((lane & 3) == 0) {
                    sRed[0][bb][wC] = se;
                    sRed[1][bb][wC] = cn;
                    sRed[2][bb][wC] = ss;
                }
            }
        }
    }

    __syncthreads();
    if (tid < BSZ) {
        g_pse[tid * NBLK + blockIdx.x] =
            sRed[0][tid][0] + sRed[0][tid][1] + sRed[0][tid][2] + sRed[0][tid][3];
        g_pcn[tid * NBLK + blockIdx.x] =
            sRed[1][tid][0] + sRed[1][tid][1] + sRed[1][tid][2] + sRed[1][tid][3];
        g_pss[tid * NBLK + blockIdx.x] =
            sRed[2][tid][0] + sRed[2][tid][1] + sRed[2][tid][2] + sRed[2][tid][3];
    }
}

// ---------------------------------------------------------------------------
// K2: fused scatter + loss.
// Blocks 0..127: EMA scatter chains (O(1) head detection via smem + ballot).
// Block 128: reduce partials, write ks and final loss mean.
// ---------------------------------------------------------------------------
__global__ __launch_bounds__(256) void scatter_loss_kernel(const float* __restrict__ inputs,
                                                           const int* __restrict__ targets,
                                                           const int* __restrict__ epoch,
                                                           float* __restrict__ out_em,
                                                           float* __restrict__ out) {
    const int t = threadIdx.x;
    const int warp = t >> 5;
    const int lane = t & 31;

    if (blockIdx.x == BSZ) {
        __shared__ float sLoss[BSZ];
        for (int b = warp; b < BSZ; b += 8) {
            float se = 0.0f, cn = 0.0f, ss = 0.0f;
#pragma unroll
            for (int i = lane; i < NBLK; i += 32) {
                se += g_pse[b * NBLK + i];
                cn += g_pcn[b * NBLK + i];
                ss += g_pss[b * NBLK + i];
            }
#pragma unroll
            for (int o = 16; o; o >>= 1) {
                se += __shfl_xor_sync(~0u, se, o);
                cn += __shfl_xor_sync(~0u, cn, o);
                ss += __shfl_xor_sync(~0u, ss, o);
            }
            if (lane == 0) {
                float st = g_st[b];
                float lse = 20.0f + logf(se);
                float logpt = st - lse;
                int n = (int)(cn + 0.5f);
                float loss;
                if (n > 1) {
                    float kk = 1.0f / ((float)n * logf((float)n));
                    int ta = (st > THRESH) ? 1 : 0;
                    float extra = kk * ((ss - (ta ? st : 0.0f)) - (float)(n - ta) * lse);
                    loss = -(extra + logpt);
                } else {
                    loss = -logpt;
                }
                sLoss[b] = loss;
                out[1 + b] = cn;  // ks
            }
        }
        __syncthreads();
        if (t == 0) {
            float acc = 0.0f;
            for (int i = 0; i < BSZ; i++) acc += sLoss[i];
            out[0] = acc / (float)BSZ;
        }
        return;
    }

    // ---- scatter block ----
    __shared__ int sT[BSZ];
    __shared__ float red[8];
    __shared__ float bc;
    if (t < BSZ) sT[t] = targets[t];
    __syncthreads();

    const int b = blockIdx.x;
    const int y = sT[b];
    int match = (t < b && sT[t] == y) ? 1 : 0;
    if (__syncthreads_or(match)) return;  // not the chain head (uniform)

    const float mu = fminf(0.4f / 60.0f * (float)(epoch[0] + 1), 1.0f);
    const float omu = 1.0f - mu;

    const size_t rbase = (size_t)y * DIM + t * 4;
    float row[4];
#pragma unroll
    for (int q = 0; q < 4; q++) row[q] = out_em[rbase + q];  // scalar: base 4 mod 16

    for (int j = b; j < BSZ; j++) {
        if (sT[j] != y) continue;  // uniform across block (smem)
        float4 x = *reinterpret_cast<const float4*>(&inputs[(size_t)j * DIM + t * 4]);
        float v0 = mu * row[0] + omu * x.x;
        float v1 = mu * row[1] + omu * x.y;
        float v2 = mu * row[2] + omu * x.z;
        float v3 = mu * row[3] + omu * x.w;
        float sq = v0 * v0 + v1 * v1 + v2 * v2 + v3 * v3;
#pragma unroll
        for (int o = 16; o; o >>= 1) sq += __shfl_xor_sync(~0u, sq, o);
        if (lane == 0) red[warp] = sq;
        __syncthreads();
        if (t == 0) {
            float s = 0.0f;
#pragma unroll
            for (int i = 0; i < 8; i++) s += red[i];
            bc = s;
        }
        __syncthreads();
        float rn = rsqrtf(bc);
        row[0] = v0 * rn; row[1] = v1 * rn; row[2] = v2 * rn; row[3] = v3 * rn;
    }
#pragma unroll
    for (int q = 0; q < 4; q++) out_em[rbase + q] = row[q];
}

// ---------------------------------------------------------------------------
// Entry point. Output layout (float32): [loss(1), ks(128), new_em(32768*1024)]
// ---------------------------------------------------------------------------
extern "C" void kernel_launch(void* const* d_in, const int* in_sizes, int n_in,
                              void* d_out, int out_size) {
    const float* inputs = (const float*)d_in[0];
    const float* em = (const float*)d_in[1];
    const int* targets = (const int*)d_in[2];
    const int* epoch = (const int*)d_in[3];
    float* out = (float*)d_out;
    float* out_em = out + 1 + BSZ;

    static bool attr_set = false;
    if (!attr_set) {
        cudaFuncSetAttribute(gemm_fused_kernel,
                             cudaFuncAttributeMaxDynamicSharedMemorySize, SMEM_DYN);
        attr_set = true;
    }

    convert_inputs_kernel<<<128, 256>>>(inputs);
    gemm_fused_kernel<<<NBLK, NTHREADS, SMEM_DYN>>>(em, out_em, targets);
    scatter_loss_kernel<<<BSZ + 1, 256>>>(inputs, targets, epoch, out_em, out);
}